// round 1
// baseline (speedup 1.0000x reference)
#include <cuda_runtime.h>
#include <cuda_fp16.h>
#include <mma.h>

using namespace nvcuda;

#define D   512
#define E   16
#define H1  128
#define H2  64
#define R   32
#define C1  (E * H1)   // 2048
#define C2  (E * H2)   // 1024
#define NMAX 65536

// ---------------- scratch (device globals: allocation-free) ----------------
__device__ float g_h1[(size_t)NMAX * C1];   // 512 MB
__device__ float g_h2[(size_t)NMAX * C2];   // 256 MB
__device__ float g_gate[(size_t)NMAX * E];
__device__ float g_sum1[C1], g_ssq1[C1], g_mean1[C1], g_inv1[C1];
__device__ float g_sum2[C2], g_ssq2[C2], g_mean2[C2], g_inv2[C2];
__device__ float g_v[E * H2];

// ---------------- small kernels ----------------
__global__ void zero_stats() {
    int i = blockIdx.x * blockDim.x + threadIdx.x;
    if (i < C1) { g_sum1[i] = 0.f; g_ssq1[i] = 0.f; }
    if (i < C2) { g_sum2[i] = 0.f; g_ssq2[i] = 0.f; }
}

__global__ void compute_v(const float* __restrict__ W3, const float* __restrict__ Ws) {
    int i = threadIdx.x;  // 0..1023 == e*64+k
    float a = 0.f;
#pragma unroll
    for (int r = 0; r < R; ++r) a += W3[(size_t)i * R + r] * Ws[r];
    g_v[i] = a;
}

// gating: g = x@Wg + bg; LayerNorm over E; softmax over E
__global__ void __launch_bounds__(256) gate_kernel(
    const float* __restrict__ x, const float* __restrict__ Wg,
    const float* __restrict__ bg, const float* __restrict__ gamma_,
    const float* __restrict__ beta_) {
    __shared__ float xs[16][D];
    const int tid = threadIdx.x;
    const size_t row0 = (size_t)blockIdx.x * 16;

    const float4* xg = reinterpret_cast<const float4*>(x + row0 * D);
    float4* xsv = reinterpret_cast<float4*>(&xs[0][0]);
#pragma unroll
    for (int i = 0; i < 8; ++i) xsv[tid + i * 256] = xg[tid + i * 256];
    __syncthreads();

    const int e = tid & 15, r = tid >> 4;
    float g = 0.f;
#pragma unroll 8
    for (int d = 0; d < D; ++d) g += xs[r][d] * Wg[d * E + e];
    g += bg[e];

    // LayerNorm over the 16-lane segment
    float mu = g;
#pragma unroll
    for (int o = 8; o; o >>= 1) mu += __shfl_xor_sync(0xffffffffu, mu, o, 16);
    mu *= (1.f / 16.f);
    float dv = g - mu;
    float vv = dv * dv;
#pragma unroll
    for (int o = 8; o; o >>= 1) vv += __shfl_xor_sync(0xffffffffu, vv, o, 16);
    vv *= (1.f / 16.f);
    g = dv * rsqrtf(vv + 1e-5f) * gamma_[e] + beta_[e];

    // softmax over 16
    float mx = g;
#pragma unroll
    for (int o = 8; o; o >>= 1) mx = fmaxf(mx, __shfl_xor_sync(0xffffffffu, mx, o, 16));
    float ex = __expf(g - mx);
    float s = ex;
#pragma unroll
    for (int o = 8; o; o >>= 1) s += __shfl_xor_sync(0xffffffffu, s, o, 16);
    g_gate[(row0 + r) * E + e] = ex / s;
}

// ---------------- GEMM1: h1 = x @ W1[e]  (f16 wmma, f32 accum) ----------------
__global__ void __launch_bounds__(256) gemm1_kernel(const float* __restrict__ x,
                                                    const float* __restrict__ W1) {
    const int e = blockIdx.y;
    const size_t m0 = (size_t)blockIdx.x * 128;
    const float* __restrict__ Bp = W1 + (size_t)e * (D * H1);

    __shared__ __half As[2][128][40];
    __shared__ __half Bs[2][32][136];

    const int tid = threadIdx.x;
    const int warp = tid >> 5;
    const int wm = warp & 3;    // 4 warps over M
    const int wn = warp >> 2;   // 2 warps over N

    wmma::fragment<wmma::accumulator, 16, 16, 16, float> acc[2][4];
#pragma unroll
    for (int i = 0; i < 2; ++i)
#pragma unroll
        for (int j = 0; j < 4; ++j) wmma::fill_fragment(acc[i][j], 0.0f);

    const int ar = tid >> 3;          // 0..31
    const int ac = (tid & 7) * 4;     // 0..28
    const int br = tid >> 5;          // 0..7
    const int bc = (tid & 31) * 4;    // 0..124

    float4 aq[4], bq[4];

    auto ldA = [&](int k0) {
#pragma unroll
        for (int i = 0; i < 4; ++i)
            aq[i] = *reinterpret_cast<const float4*>(&x[(m0 + ar + i * 32) * D + k0 + ac]);
    };
    auto ldB = [&](int k0) {
#pragma unroll
        for (int i = 0; i < 4; ++i)
            bq[i] = *reinterpret_cast<const float4*>(&Bp[(size_t)(k0 + br + i * 8) * H1 + bc]);
    };
    auto stA = [&](int buf) {
#pragma unroll
        for (int i = 0; i < 4; ++i) {
            __half* p = &As[buf][ar + i * 32][ac];
            p[0] = __float2half_rn(aq[i].x); p[1] = __float2half_rn(aq[i].y);
            p[2] = __float2half_rn(aq[i].z); p[3] = __float2half_rn(aq[i].w);
        }
    };
    auto stB = [&](int buf) {
#pragma unroll
        for (int i = 0; i < 4; ++i) {
            __half* p = &Bs[buf][br + i * 8][bc];
            p[0] = __float2half_rn(bq[i].x); p[1] = __float2half_rn(bq[i].y);
            p[2] = __float2half_rn(bq[i].z); p[3] = __float2half_rn(bq[i].w);
        }
    };

    ldA(0); ldB(0);
    stA(0); stB(0);
    __syncthreads();

    for (int kt = 0; kt < 16; ++kt) {
        const int cur = kt & 1;
        if (kt < 15) { ldA((kt + 1) * 32); ldB((kt + 1) * 32); }
#pragma unroll
        for (int kk = 0; kk < 2; ++kk) {
            wmma::fragment<wmma::matrix_a, 16, 16, 16, __half, wmma::row_major> af[2];
            wmma::fragment<wmma::matrix_b, 16, 16, 16, __half, wmma::row_major> bf[4];
#pragma unroll
            for (int i = 0; i < 2; ++i)
                wmma::load_matrix_sync(af[i], &As[cur][wm * 32 + i * 16][kk * 16], 40);
#pragma unroll
            for (int j = 0; j < 4; ++j)
                wmma::load_matrix_sync(bf[j], &Bs[cur][kk * 16][wn * 64 + j * 16], 136);
#pragma unroll
            for (int i = 0; i < 2; ++i)
#pragma unroll
                for (int j = 0; j < 4; ++j)
                    wmma::mma_sync(acc[i][j], af[i], bf[j], acc[i][j]);
        }
        if (kt < 15) { stA(cur ^ 1); stB(cur ^ 1); }
        __syncthreads();
    }

    float* outp = g_h1 + m0 * C1 + (size_t)e * H1;
#pragma unroll
    for (int i = 0; i < 2; ++i)
#pragma unroll
        for (int j = 0; j < 4; ++j)
            wmma::store_matrix_sync(&outp[(size_t)(wm * 32 + i * 16) * C1 + wn * 64 + j * 16],
                                    acc[i][j], C1, wmma::mem_row_major);
}

// ---------------- column stats (sum, sumsq) over N ----------------
template <int NCOLS>
__global__ void __launch_bounds__(256) colstats_kernel(int rows_per_block) {
    constexpr int NPER = NCOLS / 256;
    const float* __restrict__ data = (NCOLS == C1) ? g_h1 : g_h2;
    float* __restrict__ sum = (NCOLS == C1) ? g_sum1 : g_sum2;
    float* __restrict__ ssq = (NCOLS == C1) ? g_ssq1 : g_ssq2;

    float s[NPER], q[NPER];
#pragma unroll
    for (int i = 0; i < NPER; ++i) { s[i] = 0.f; q[i] = 0.f; }

    const size_t r0 = (size_t)blockIdx.x * rows_per_block;
    for (int r = 0; r < rows_per_block; ++r) {
        const float* row = data + (r0 + r) * NCOLS;
#pragma unroll
        for (int i = 0; i < NPER; ++i) {
            float v = row[threadIdx.x + i * 256];
            s[i] += v;
            q[i] = fmaf(v, v, q[i]);
        }
    }
#pragma unroll
    for (int i = 0; i < NPER; ++i) {
        atomicAdd(&sum[threadIdx.x + i * 256], s[i]);
        atomicAdd(&ssq[threadIdx.x + i * 256], q[i]);
    }
}

template <int NCOLS>
__global__ void finalize_kernel(float invN) {
    int c = blockIdx.x * 256 + threadIdx.x;
    if (c < NCOLS) {
        const float* sum = (NCOLS == C1) ? g_sum1 : g_sum2;
        const float* ssq = (NCOLS == C1) ? g_ssq1 : g_ssq2;
        float* mean = (NCOLS == C1) ? g_mean1 : g_mean2;
        float* inv  = (NCOLS == C1) ? g_inv1  : g_inv2;
        float m = sum[c] * invN;
        float var = fmaxf(ssq[c] * invN - m * m, 0.f);
        mean[c] = m;
        inv[c] = rsqrtf(var + 1e-4f);
    }
}

// ---------------- GEMM2: h2 = bn_lrelu(h1[e]) @ W2[e] ----------------
__global__ void __launch_bounds__(256) gemm2_kernel(const float* __restrict__ W2) {
    const int e = blockIdx.y;
    const size_t m0 = (size_t)blockIdx.x * 128;
    const float* __restrict__ Bp = W2 + (size_t)e * (H1 * H2);

    __shared__ __half As[2][128][40];
    __shared__ __half Bs[2][32][72];
    __shared__ float msh[H1], ish[H1];

    const int tid = threadIdx.x;
    if (tid < H1) { msh[tid] = g_mean1[e * H1 + tid]; ish[tid] = g_inv1[e * H1 + tid]; }

    const int warp = tid >> 5;
    const int wm = warp & 3;
    const int wn = warp >> 2;

    wmma::fragment<wmma::accumulator, 16, 16, 16, float> acc[2][2];
#pragma unroll
    for (int i = 0; i < 2; ++i)
#pragma unroll
        for (int j = 0; j < 2; ++j) wmma::fill_fragment(acc[i][j], 0.0f);

    const int ar = tid >> 3;        // 0..31
    const int ac = (tid & 7) * 4;   // 0..28
    const int br = tid >> 4;        // 0..15
    const int bc = (tid & 15) * 4;  // 0..60

    float4 aq[4], bq[2];

    auto ldA = [&](int k0) {
#pragma unroll
        for (int i = 0; i < 4; ++i)
            aq[i] = *reinterpret_cast<const float4*>(
                &g_h1[(m0 + ar + i * 32) * C1 + (size_t)e * H1 + k0 + ac]);
    };
    auto ldB = [&](int k0) {
#pragma unroll
        for (int i = 0; i < 2; ++i)
            bq[i] = *reinterpret_cast<const float4*>(&Bp[(size_t)(k0 + br + i * 16) * H2 + bc]);
    };
    auto stA = [&](int buf, int k0) {
#pragma unroll
        for (int i = 0; i < 4; ++i) {
            float vals[4] = {aq[i].x, aq[i].y, aq[i].z, aq[i].w};
            __half* p = &As[buf][ar + i * 32][ac];
#pragma unroll
            for (int t = 0; t < 4; ++t) {
                float a = (vals[t] - msh[k0 + ac + t]) * ish[k0 + ac + t];
                a = (a >= 0.f) ? a : 0.01f * a;
                p[t] = __float2half_rn(a);
            }
        }
    };
    auto stB = [&](int buf) {
#pragma unroll
        for (int i = 0; i < 2; ++i) {
            __half* p = &Bs[buf][br + i * 16][bc];
            p[0] = __float2half_rn(bq[i].x); p[1] = __float2half_rn(bq[i].y);
            p[2] = __float2half_rn(bq[i].z); p[3] = __float2half_rn(bq[i].w);
        }
    };

    ldA(0); ldB(0);
    __syncthreads();       // msh/ish visible
    stA(0, 0); stB(0);
    __syncthreads();

    for (int kt = 0; kt < 4; ++kt) {
        const int cur = kt & 1;
        if (kt < 3) { ldA((kt + 1) * 32); ldB((kt + 1) * 32); }
#pragma unroll
        for (int kk = 0; kk < 2; ++kk) {
            wmma::fragment<wmma::matrix_a, 16, 16, 16, __half, wmma::row_major> af[2];
            wmma::fragment<wmma::matrix_b, 16, 16, 16, __half, wmma::row_major> bf[2];
#pragma unroll
            for (int i = 0; i < 2; ++i)
                wmma::load_matrix_sync(af[i], &As[cur][wm * 32 + i * 16][kk * 16], 40);
#pragma unroll
            for (int j = 0; j < 2; ++j)
                wmma::load_matrix_sync(bf[j], &Bs[cur][kk * 16][wn * 32 + j * 16], 72);
#pragma unroll
            for (int i = 0; i < 2; ++i)
#pragma unroll
                for (int j = 0; j < 2; ++j)
                    wmma::mma_sync(acc[i][j], af[i], bf[j], acc[i][j]);
        }
        if (kt < 3) { stA(cur ^ 1, (kt + 1) * 32); stB(cur ^ 1); }
        __syncthreads();
    }

    float* outp = g_h2 + m0 * C2 + (size_t)e * H2;
#pragma unroll
    for (int i = 0; i < 2; ++i)
#pragma unroll
        for (int j = 0; j < 2; ++j)
            wmma::store_matrix_sync(&outp[(size_t)(wm * 32 + i * 16) * C2 + wn * 32 + j * 16],
                                    acc[i][j], C2, wmma::mem_row_major);
}

// ---------------- final: out[n] = sum_e gate * (bn_lrelu(h2) . v[e] + bs) ----------------
__global__ void __launch_bounds__(256) final_kernel(const float* __restrict__ bs_p,
                                                    float* __restrict__ out) {
    const int tid = threadIdx.x;
    const int e = tid & 15, r = tid >> 4;
    const size_t row = (size_t)blockIdx.x * 16 + r;

    const float* hp = g_h2 + row * C2 + (size_t)e * H2;
    const float* mp = g_mean2 + e * H2;
    const float* ip = g_inv2 + e * H2;
    const float* vp = g_v + e * H2;

    float acc = 0.f;
#pragma unroll
    for (int k = 0; k < H2; k += 4) {
        float4 h = *reinterpret_cast<const float4*>(&hp[k]);
        float a;
        a = (h.x - mp[k])     * ip[k];     a = (a >= 0.f) ? a : 0.01f * a; acc = fmaf(a, vp[k],     acc);
        a = (h.y - mp[k + 1]) * ip[k + 1]; a = (a >= 0.f) ? a : 0.01f * a; acc = fmaf(a, vp[k + 1], acc);
        a = (h.z - mp[k + 2]) * ip[k + 2]; a = (a >= 0.f) ? a : 0.01f * a; acc = fmaf(a, vp[k + 2], acc);
        a = (h.w - mp[k + 3]) * ip[k + 3]; a = (a >= 0.f) ? a : 0.01f * a; acc = fmaf(a, vp[k + 3], acc);
    }
    float contrib = g_gate[row * E + e] * (acc + bs_p[0]);
#pragma unroll
    for (int o = 8; o; o >>= 1) contrib += __shfl_down_sync(0xffffffffu, contrib, o, 16);
    if (e == 0) out[row] = contrib;
}

// ---------------- launch ----------------
extern "C" void kernel_launch(void* const* d_in, const int* in_sizes, int n_in,
                              void* d_out, int out_size) {
    const float* x  = (const float*)d_in[0];
    const float* Wg = (const float*)d_in[1];
    const float* bg = (const float*)d_in[2];
    const float* ga = (const float*)d_in[3];
    const float* be = (const float*)d_in[4];
    const float* W1 = (const float*)d_in[5];
    const float* W2 = (const float*)d_in[6];
    const float* W3 = (const float*)d_in[7];
    const float* Ws = (const float*)d_in[8];
    const float* bs = (const float*)d_in[9];
    float* out = (float*)d_out;

    const int N = in_sizes[0] / D;        // 65536
    const int mtiles = N / 128;           // 512
    const float invN = 1.0f / (float)N;
    const int stat_blocks = 512;
    const int rows_per_block = N / stat_blocks;

    zero_stats<<<8, 256>>>();
    compute_v<<<1, C2>>>(W3, Ws);
    gate_kernel<<<N / 16, 256>>>(x, Wg, bg, ga, be);

    gemm1_kernel<<<dim3(mtiles, E), 256>>>(x, W1);
    colstats_kernel<C1><<<stat_blocks, 256>>>(rows_per_block);
    finalize_kernel<C1><<<(C1 + 255) / 256, 256>>>(invN);

    gemm2_kernel<<<dim3(mtiles, E), 256>>>(W2);
    colstats_kernel<C2><<<stat_blocks, 256>>>(rows_per_block);
    finalize_kernel<C2><<<(C2 + 255) / 256, 256>>>(invN);

    final_kernel<<<N / 16, 256>>>(bs, out);
}

// round 3
// speedup vs baseline: 1.3113x; 1.3113x over previous
#include <cuda_runtime.h>
#include <cuda_fp16.h>
#include <mma.h>
#include <cstdint>

using namespace nvcuda;

#define D   512
#define E   16
#define H1  128
#define H2  64
#define R   32
#define C1  (E * H1)   // 2048
#define C2  (E * H2)   // 1024
#define NMAX 65536

// ---------------- scratch (device globals: allocation-free) ----------------
__device__ __half g_x16[(size_t)NMAX * D];       // 64 MB
__device__ __half g_W1p[(size_t)D * C1];         // 2 MB   [d][e*128+j]
__device__ __half g_W2p[(size_t)E * H1 * H2];    // 256 KB [e][k][j]
__device__ __half g_h1[(size_t)NMAX * C1];       // 256 MB
__device__ __half g_h2[(size_t)NMAX * C2];       // 128 MB
__device__ float  g_gate[(size_t)NMAX * E];
__device__ float  g_sum1[C1], g_ssq1[C1], g_mean1[C1], g_inv1[C1];
__device__ float  g_sum2[C2], g_ssq2[C2], g_mean2[C2], g_inv2[C2];
__device__ float  g_v[E * H2];

// ---------------- cp.async helpers ----------------
__device__ __forceinline__ void cp_async16(void* smem, const void* gmem) {
    unsigned int s = (unsigned int)__cvta_generic_to_shared(smem);
    asm volatile("cp.async.cg.shared.global [%0], [%1], 16;\n" :: "r"(s), "l"(gmem));
}
__device__ __forceinline__ void cp_commit() {
    asm volatile("cp.async.commit_group;\n");
}
template <int NN>
__device__ __forceinline__ void cp_wait() {
    asm volatile("cp.async.wait_group %0;\n" :: "n"(NN));
}

// ---------------- small kernels ----------------
__global__ void zero_stats() {
    int i = blockIdx.x * blockDim.x + threadIdx.x;
    if (i < C1) { g_sum1[i] = 0.f; g_ssq1[i] = 0.f; }
    if (i < C2) { g_sum2[i] = 0.f; g_ssq2[i] = 0.f; }
}

__global__ void compute_v(const float* __restrict__ W3, const float* __restrict__ Ws) {
    int i = threadIdx.x;  // 0..1023 == e*64+k
    float a = 0.f;
#pragma unroll
    for (int r = 0; r < R; ++r) a += W3[(size_t)i * R + r] * Ws[r];
    g_v[i] = a;
}

__global__ void __launch_bounds__(256) convert_x(const float* __restrict__ x, int total8) {
    int idx = blockIdx.x * 256 + threadIdx.x;
    if (idx >= total8) return;
    const float4* xp = reinterpret_cast<const float4*>(x) + (size_t)idx * 2;
    float4 a = xp[0], b = xp[1];
    __half2 h[4];
    h[0] = __floats2half2_rn(a.x, a.y);
    h[1] = __floats2half2_rn(a.z, a.w);
    h[2] = __floats2half2_rn(b.x, b.y);
    h[3] = __floats2half2_rn(b.z, b.w);
    *(reinterpret_cast<float4*>(g_x16) + idx) = *reinterpret_cast<float4*>(h);
}

__global__ void __launch_bounds__(256) pack_W1(const float* __restrict__ W1) {
    int idx = blockIdx.x * 256 + threadIdx.x;   // over E*D*H1 = 1M
    if (idx >= E * D * H1) return;
    int j = idx & (H1 - 1);
    int d = (idx >> 7) & (D - 1);
    int e = idx >> 16;
    g_W1p[(size_t)d * C1 + e * H1 + j] = __float2half_rn(W1[idx]);
}

__global__ void __launch_bounds__(256) pack_W2(const float* __restrict__ W2) {
    int idx = blockIdx.x * 256 + threadIdx.x;   // over E*H1*H2 = 131072
    if (idx >= E * H1 * H2) return;
    g_W2p[idx] = __float2half_rn(W2[idx]);
}

// gating: g = x@Wg + bg; LayerNorm over E; softmax over E
__global__ void __launch_bounds__(256) gate_kernel(
    const float* __restrict__ x, const float* __restrict__ Wg,
    const float* __restrict__ bg, const float* __restrict__ gamma_,
    const float* __restrict__ beta_) {
    __shared__ float xs[16][D];
    const int tid = threadIdx.x;
    const size_t row0 = (size_t)blockIdx.x * 16;

    const float4* xg = reinterpret_cast<const float4*>(x + row0 * D);
    float4* xsv = reinterpret_cast<float4*>(&xs[0][0]);
#pragma unroll
    for (int i = 0; i < 8; ++i) xsv[tid + i * 256] = xg[tid + i * 256];
    __syncthreads();

    const int e = tid & 15, r = tid >> 4;
    float g = 0.f;
#pragma unroll 8
    for (int d = 0; d < D; ++d) g += xs[r][d] * Wg[d * E + e];
    g += bg[e];

    float mu = g;
#pragma unroll
    for (int o = 8; o; o >>= 1) mu += __shfl_xor_sync(0xffffffffu, mu, o, 16);
    mu *= (1.f / 16.f);
    float dv = g - mu;
    float vv = dv * dv;
#pragma unroll
    for (int o = 8; o; o >>= 1) vv += __shfl_xor_sync(0xffffffffu, vv, o, 16);
    vv *= (1.f / 16.f);
    g = dv * rsqrtf(vv + 1e-5f) * gamma_[e] + beta_[e];

    float mx = g;
#pragma unroll
    for (int o = 8; o; o >>= 1) mx = fmaxf(mx, __shfl_xor_sync(0xffffffffu, mx, o, 16));
    float ex = __expf(g - mx);
    float s = ex;
#pragma unroll
    for (int o = 8; o; o >>= 1) s += __shfl_xor_sync(0xffffffffu, s, o, 16);
    g_gate[(row0 + r) * E + e] = ex / s;
}

// ---------------- GEMM1: h1 = x16 @ W1p  (single GEMM 65536x2048x512) ----------------
// blockIdx.x = ntile (16), blockIdx.y = mtile -> consecutive CTAs share the x tile in L2.
// tile 128x128, KTILE=32, 3-stage cp.async pipeline. Epilogue: C -> smem, stats atomics,
// fp16 h1 store.
#define G1_STAGE_BYTES (128 * 40 * 2 + 32 * 136 * 2)   // 10240 + 8704 = 18944
#define G1_SMEM (128 * 132 * 4)                        // 67584 > 3*18944

__global__ void __launch_bounds__(256) gemm1_kernel() {
    extern __shared__ char smbuf[];
    const int n0 = blockIdx.x * 128;
    const size_t m0 = (size_t)blockIdx.y * 128;

    const int tid = threadIdx.x;
    const int warp = tid >> 5;
    const int wm = warp & 3;
    const int wn = warp >> 2;

    wmma::fragment<wmma::accumulator, 16, 16, 16, float> acc[2][4];
#pragma unroll
    for (int i = 0; i < 2; ++i)
#pragma unroll
        for (int j = 0; j < 4; ++j) wmma::fill_fragment(acc[i][j], 0.0f);

    auto As = [&](int s) { return reinterpret_cast<__half*>(smbuf + s * G1_STAGE_BYTES); };
    auto Bs = [&](int s) { return reinterpret_cast<__half*>(smbuf + s * G1_STAGE_BYTES + 128 * 40 * 2); };

    // A tile 128x32: 512 16B-chunks; B tile 32x128: 512 chunks. 2 each per thread.
    auto issue = [&](int kt, int s) {
        const int k0 = kt * 32;
        __half* a = As(s);
        __half* b = Bs(s);
#pragma unroll
        for (int i = 0; i < 2; ++i) {
            int c = tid + i * 256;
            int r = c >> 2, col = (c & 3) * 8;
            cp_async16(a + r * 40 + col, g_x16 + (m0 + r) * D + k0 + col);
        }
#pragma unroll
        for (int i = 0; i < 2; ++i) {
            int c = tid + i * 256;
            int r = c >> 4, col = (c & 15) * 8;
            cp_async16(b + r * 136 + col, g_W1p + (size_t)(k0 + r) * C1 + n0 + col);
        }
        cp_commit();
    };

    issue(0, 0);
    issue(1, 1);

    for (int kt = 0; kt < 16; ++kt) {
        if (kt < 15) cp_wait<1>(); else cp_wait<0>();
        __syncthreads();
        if (kt + 2 < 16) issue(kt + 2, (kt + 2) % 3);

        const __half* a = As(kt % 3);
        const __half* b = Bs(kt % 3);
#pragma unroll
        for (int kk = 0; kk < 2; ++kk) {
            wmma::fragment<wmma::matrix_a, 16, 16, 16, __half, wmma::row_major> af[2];
            wmma::fragment<wmma::matrix_b, 16, 16, 16, __half, wmma::row_major> bf[4];
#pragma unroll
            for (int i = 0; i < 2; ++i)
                wmma::load_matrix_sync(af[i], a + (wm * 32 + i * 16) * 40 + kk * 16, 40);
#pragma unroll
            for (int j = 0; j < 4; ++j)
                wmma::load_matrix_sync(bf[j], b + (kk * 16) * 136 + wn * 64 + j * 16, 136);
#pragma unroll
            for (int i = 0; i < 2; ++i)
#pragma unroll
                for (int j = 0; j < 4; ++j)
                    wmma::mma_sync(acc[i][j], af[i], bf[j], acc[i][j]);
        }
    }

    // ---- epilogue: stage C in smem, stats + fp16 store ----
    __syncthreads();
    float* Cs = reinterpret_cast<float*>(smbuf);  // [128][132]
#pragma unroll
    for (int i = 0; i < 2; ++i)
#pragma unroll
        for (int j = 0; j < 4; ++j)
            wmma::store_matrix_sync(Cs + (wm * 32 + i * 16) * 132 + wn * 64 + j * 16,
                                    acc[i][j], 132, wmma::mem_row_major);
    __syncthreads();

    // stats: 2 threads per column, 64 rows each
    {
        int c = tid & 127, hf = tid >> 7;
        float s = 0.f, q = 0.f;
#pragma unroll 8
        for (int r = hf * 64; r < hf * 64 + 64; ++r) {
            float v = Cs[r * 132 + c];
            s += v;
            q = fmaf(v, v, q);
        }
        atomicAdd(&g_sum1[n0 + c], s);
        atomicAdd(&g_ssq1[n0 + c], q);
    }

    // fp16 store: 8192 half2 pairs / 256 threads
#pragma unroll
    for (int i = 0; i < 32; ++i) {
        int pid = tid + i * 256;
        int r = pid >> 6, c2 = pid & 63;
        __half2 h = __floats2half2_rn(Cs[r * 132 + 2 * c2], Cs[r * 132 + 2 * c2 + 1]);
        *reinterpret_cast<__half2*>(g_h1 + (m0 + r) * C1 + n0 + 2 * c2) = h;
    }
}

template <int NCOLS>
__global__ void finalize_kernel(float invN) {
    int c = blockIdx.x * 256 + threadIdx.x;
    if (c < NCOLS) {
        const float* sum = (NCOLS == C1) ? g_sum1 : g_sum2;
        const float* ssq = (NCOLS == C1) ? g_ssq1 : g_ssq2;
        float* mean = (NCOLS == C1) ? g_mean1 : g_mean2;
        float* inv  = (NCOLS == C1) ? g_inv1  : g_inv2;
        float m = sum[c] * invN;
        float var = fmaxf(ssq[c] * invN - m * m, 0.f);
        mean[c] = m;
        inv[c] = rsqrtf(var + 1e-4f);
    }
}

// ---------------- GEMM2: h2 = bn_lrelu(h1[e]) @ W2[e]  (K=128 one-shot) ----------------
// blockIdx.x = expert (16), blockIdx.y = mtile. tile 128x64.
#define G2_A_BYTES (128 * 136 * 2)   // 34816
#define G2_B_BYTES (128 * 72 * 2)    // 18432
#define G2_SMEM (G2_A_BYTES + G2_B_BYTES + 128 * 2 * 4)  // 54272

__global__ void __launch_bounds__(256) gemm2_kernel() {
    extern __shared__ char smbuf[];
    const int e = blockIdx.x;
    const size_t m0 = (size_t)blockIdx.y * 128;
    const int tid = threadIdx.x;

    __half* A = reinterpret_cast<__half*>(smbuf);                 // [128][136]
    __half* B = reinterpret_cast<__half*>(smbuf + G2_A_BYTES);    // [128][72]
    float* msh = reinterpret_cast<float*>(smbuf + G2_A_BYTES + G2_B_BYTES);
    float* ish = msh + 128;

    // async loads: A (h1 expert columns) 2048 chunks, B (W2) 1024 chunks
#pragma unroll
    for (int i = 0; i < 8; ++i) {
        int c = tid + i * 256;
        int r = c >> 4, col = (c & 15) * 8;
        cp_async16(A + r * 136 + col, g_h1 + (m0 + r) * C1 + e * H1 + col);
    }
#pragma unroll
    for (int i = 0; i < 4; ++i) {
        int c = tid + i * 256;
        int r = c >> 3, col = (c & 7) * 8;
        cp_async16(B + r * 72 + col, g_W2p + (size_t)e * H1 * H2 + r * H2 + col);
    }
    cp_commit();
    if (tid < 128) {
        msh[tid] = g_mean1[e * H1 + tid];
        ish[tid] = g_inv1[e * H1 + tid];
    }
    cp_wait<0>();
    __syncthreads();

    // in-place BN + leaky relu on A (fp32 math, fp16 result)
#pragma unroll
    for (int i = 0; i < 32; ++i) {
        int pid = tid + i * 256;
        int r = pid >> 6, c2 = pid & 63;
        __half2* p = reinterpret_cast<__half2*>(A + r * 136 + 2 * c2);
        float2 v = __half22float2(*p);
        float a0 = (v.x - msh[2 * c2]) * ish[2 * c2];
        float a1 = (v.y - msh[2 * c2 + 1]) * ish[2 * c2 + 1];
        a0 = (a0 >= 0.f) ? a0 : 0.01f * a0;
        a1 = (a1 >= 0.f) ? a1 : 0.01f * a1;
        *p = __floats2half2_rn(a0, a1);
    }
    __syncthreads();

    const int warp = tid >> 5;
    const int wm = warp & 3;
    const int wn = warp >> 2;

    wmma::fragment<wmma::accumulator, 16, 16, 16, float> acc[2][2];
#pragma unroll
    for (int i = 0; i < 2; ++i)
#pragma unroll
        for (int j = 0; j < 2; ++j) wmma::fill_fragment(acc[i][j], 0.0f);

#pragma unroll
    for (int kk = 0; kk < 8; ++kk) {
        wmma::fragment<wmma::matrix_a, 16, 16, 16, __half, wmma::row_major> af[2];
        wmma::fragment<wmma::matrix_b, 16, 16, 16, __half, wmma::row_major> bf[2];
#pragma unroll
        for (int i = 0; i < 2; ++i)
            wmma::load_matrix_sync(af[i], A + (wm * 32 + i * 16) * 136 + kk * 16, 136);
#pragma unroll
        for (int j = 0; j < 2; ++j)
            wmma::load_matrix_sync(bf[j], B + (kk * 16) * 72 + wn * 32 + j * 16, 72);
#pragma unroll
        for (int i = 0; i < 2; ++i)
#pragma unroll
            for (int j = 0; j < 2; ++j)
                wmma::mma_sync(acc[i][j], af[i], bf[j], acc[i][j]);
    }

    __syncthreads();
    float* Cs = reinterpret_cast<float*>(smbuf);  // [128][68]
#pragma unroll
    for (int i = 0; i < 2; ++i)
#pragma unroll
        for (int j = 0; j < 2; ++j)
            wmma::store_matrix_sync(Cs + (wm * 32 + i * 16) * 68 + wn * 32 + j * 16,
                                    acc[i][j], 68, wmma::mem_row_major);
    __syncthreads();

    // stats: 4 threads per column, 32 rows each
    {
        int c = tid & 63, q4 = tid >> 6;
        float s = 0.f, q = 0.f;
#pragma unroll 8
        for (int r = q4 * 32; r < q4 * 32 + 32; ++r) {
            float v = Cs[r * 68 + c];
            s += v;
            q = fmaf(v, v, q);
        }
        atomicAdd(&g_sum2[e * H2 + c], s);
        atomicAdd(&g_ssq2[e * H2 + c], q);
    }

    // fp16 store: 4096 pairs / 256 threads
#pragma unroll
    for (int i = 0; i < 16; ++i) {
        int pid = tid + i * 256;
        int r = pid >> 5, c2 = pid & 31;
        __half2 h = __floats2half2_rn(Cs[r * 68 + 2 * c2], Cs[r * 68 + 2 * c2 + 1]);
        *reinterpret_cast<__half2*>(g_h2 + (m0 + r) * C2 + e * H2 + 2 * c2) = h;
    }
}

// ---------------- final: out[n] = sum_e gate * (bn_lrelu(h2) . v[e] + bs) ----------------
__global__ void __launch_bounds__(256) final_kernel(const float* __restrict__ bs_p,
                                                    float* __restrict__ out) {
    const int tid = threadIdx.x;
    const int e = tid & 15, r = tid >> 4;
    const size_t row = (size_t)blockIdx.x * 16 + r;

    const __half2* hp = reinterpret_cast<const __half2*>(g_h2 + row * C2 + (size_t)e * H2);
    const float* mp = g_mean2 + e * H2;
    const float* ip = g_inv2 + e * H2;
    const float* vp = g_v + e * H2;

    float acc = 0.f;
#pragma unroll
    for (int k2 = 0; k2 < H2 / 2; ++k2) {
        float2 h = __half22float2(hp[k2]);
        float a;
        a = (h.x - mp[2 * k2])     * ip[2 * k2];     a = (a >= 0.f) ? a : 0.01f * a; acc = fmaf(a, vp[2 * k2],     acc);
        a = (h.y - mp[2 * k2 + 1]) * ip[2 * k2 + 1]; a = (a >= 0.f) ? a : 0.01f * a; acc = fmaf(a, vp[2 * k2 + 1], acc);
    }
    float contrib = g_gate[row * E + e] * (acc + bs_p[0]);
#pragma unroll
    for (int o = 8; o; o >>= 1) contrib += __shfl_down_sync(0xffffffffu, contrib, o, 16);
    if (e == 0) out[row] = contrib;
}

// ---------------- launch ----------------
extern "C" void kernel_launch(void* const* d_in, const int* in_sizes, int n_in,
                              void* d_out, int out_size) {
    const float* x  = (const float*)d_in[0];
    const float* Wg = (const float*)d_in[1];
    const float* bg = (const float*)d_in[2];
    const float* ga = (const float*)d_in[3];
    const float* be = (const float*)d_in[4];
    const float* W1 = (const float*)d_in[5];
    const float* W2 = (const float*)d_in[6];
    const float* W3 = (const float*)d_in[7];
    const float* Ws = (const float*)d_in[8];
    const float* bs = (const float*)d_in[9];
    float* out = (float*)d_out;

    const int N = in_sizes[0] / D;        // 65536
    const int mtiles = N / 128;           // 512
    const float invN = 1.0f / (float)N;

    static bool attr_done = false;
    if (!attr_done) {
        cudaFuncSetAttribute(gemm1_kernel, cudaFuncAttributeMaxDynamicSharedMemorySize, G1_SMEM);
        cudaFuncSetAttribute(gemm2_kernel, cudaFuncAttributeMaxDynamicSharedMemorySize, G2_SMEM);
        attr_done = true;
    }

    zero_stats<<<8, 256>>>();
    compute_v<<<1, C2>>>(W3, Ws);
    convert_x<<<(N * D / 8 + 255) / 256, 256>>>(x, N * D / 8);
    pack_W1<<<(E * D * H1 + 255) / 256, 256>>>(W1);
    pack_W2<<<(E * H1 * H2 + 255) / 256, 256>>>(W2);
    gate_kernel<<<N / 16, 256>>>(x, Wg, bg, ga, be);

    gemm1_kernel<<<dim3(C1 / 128, mtiles), 256, G1_SMEM>>>();
    finalize_kernel<C1><<<(C1 + 255) / 256, 256>>>(invN);

    gemm2_kernel<<<dim3(E, mtiles), 256, G2_SMEM>>>();
    finalize_kernel<C2><<<(C2 + 255) / 256, 256>>>(invN);

    final_kernel<<<N / 16, 256>>>(bs, out);
}